// round 17
// baseline (speedup 1.0000x reference)
#include <cuda_runtime.h>
#include <cuda_fp16.h>
#include <cstdint>
#include <cstring>

#define N_NODES   100000
#define N_EDGES   1600000
#define D         64
#define NEG_SLOPE 0.2f
#define BUCKET    64        // max in-degree slots (Poisson(16): P(>64) ~ 1e-29)

// packed fp16x2 FMA / ADD
#define HFMA2(d, a, b) \
    asm("fma.rn.f16x2 %0, %1, %2, %0;" : "+r"(d) : "r"(a), "r"(b))
#define HADD2(d, a, b) \
    asm("add.rn.f16x2 %0, %1, %2;" : "=r"(d) : "r"(a), "r"(b))

#define LDMATRIX_X4(r0, r1, r2, r3, addr) \
    asm volatile("ldmatrix.sync.aligned.m8n8.x4.shared.b16 {%0,%1,%2,%3}, [%4];" \
                 : "=r"(r0), "=r"(r1), "=r"(r2), "=r"(r3) : "r"(addr))
#define LDMATRIX_X2(r0, r1, addr) \
    asm volatile("ldmatrix.sync.aligned.m8n8.x2.shared.b16 {%0,%1}, [%2];" \
                 : "=r"(r0), "=r"(r1) : "r"(addr))

__device__ __forceinline__ uint32_t h2_bits(__half2 h) {
    uint32_t u; memcpy(&u, &h, 4); return u;
}
__device__ __forceinline__ __half2 bits_h2(uint32_t u) {
    __half2 h; memcpy(&h, &u, 4); return h;
}

// Scratch (allocation-free rule: __device__ globals)
__device__ int     g_cnt[N_NODES];                       // in-degree counters
__device__ float2  g_csr[(size_t)N_NODES * BUCKET];      // buckets (src_bits, ex)
__device__ __half2 g_gh[(size_t)N_NODES * 32];           // feat @ W_neigh^T (fp16)

// ---------------------------------------------------------------------------
// K1: single-pass bucket build (R12-proven).
// ---------------------------------------------------------------------------
__global__ void place_kernel(const float* __restrict__ rel,
                             const float* __restrict__ attn,
                             const int*   __restrict__ src,
                             const int*   __restrict__ dst) {
    int i = (blockIdx.x * blockDim.x + threadIdx.x) * 2;
    if (i >= N_EDGES) return;
    float a0 = __ldg(&attn[0]);
    float a1 = __ldg(&attn[1]);
    float4 r = *reinterpret_cast<const float4*>(rel + i * 2);  // edges i, i+1
    int2 s2 = *reinterpret_cast<const int2*>(src + i);
    int2 d2 = *reinterpret_cast<const int2*>(dst + i);

    float e0 = r.x * a0 + r.y * a1;
    float e1 = r.z * a0 + r.w * a1;
    e0 = (e0 > 0.0f) ? e0 : NEG_SLOPE * e0;
    e1 = (e1 > 0.0f) ? e1 : NEG_SLOPE * e1;
    float ex0 = __expf(e0);
    float ex1 = __expf(e1);

    int p0 = atomicAdd(&g_cnt[d2.x], 1);
    int p1 = atomicAdd(&g_cnt[d2.y], 1);
    if (p0 < BUCKET)
        g_csr[(size_t)d2.x * BUCKET + p0] = make_float2(__int_as_float(s2.x), ex0);
    if (p1 < BUCKET)
        g_csr[(size_t)d2.y * BUCKET + p1] = make_float2(__int_as_float(s2.y), ex1);
}

// ---------------------------------------------------------------------------
// K2: fused dual GEMM via mma.sync + ldmatrix, two accumulator halves.
//   Tile: 64 nodes x 128 outputs (cols 0-63 self, 64-127 neigh), K = 64.
//   A = feat (fp16, smem [64][72]); B = [Ws ; Wn] (fp16, smem [128][72], [n][k]).
//   Half 0: self cols -> out (+bias). Half 1: neigh cols -> fp16 g_gh.
//   Only 8 live accumulators/thread per half -> lower regs, higher occ.
// ---------------------------------------------------------------------------
#define APITCH 72
__global__ __launch_bounds__(128) void hmma_gemm_kernel(
    const float* __restrict__ feat,
    const float* __restrict__ Ws, const float* __restrict__ bs,
    const float* __restrict__ Wn, const float* __restrict__ bn,
    float* __restrict__ out) {
    __shared__ __half sA[64][APITCH];
    __shared__ __half sB[128][APITCH];
    __shared__ float  sBias[64];

    const int t = threadIdx.x;
    const int w = t >> 5, lane = t & 31;
    const int g = lane >> 2, tq = lane & 3;
    const int nodeBase = blockIdx.x * 64;

    if (t < 64) sBias[t] = __ldg(&bs[t]) + __ldg(&bn[t]);

    // A: feat tile, fp32 -> fp16
    for (int i = t; i < 1024; i += 128) {
        int row = i >> 4, q = i & 15;
        int node = nodeBase + row;
        float4 v = (node < N_NODES)
                       ? reinterpret_cast<const float4*>(feat)[(size_t)node * 16 + q]
                       : make_float4(0.f, 0.f, 0.f, 0.f);
        *reinterpret_cast<uint2*>(&sA[row][q * 4]) =
            make_uint2(h2_bits(__floats2half2_rn(v.x, v.y)),
                       h2_bits(__floats2half2_rn(v.z, v.w)));
    }
    // B: rows 0-63 = Ws, 64-127 = Wn  (row n holds W[n][k], k contiguous)
    for (int i = t; i < 2048; i += 128) {
        int row = i >> 4, q = i & 15;
        const float* W = (row < 64) ? Ws : Wn;
        float4 v = reinterpret_cast<const float4*>(W)[(row & 63) * 16 + q];
        *reinterpret_cast<uint2*>(&sB[row][q * 4]) =
            make_uint2(h2_bits(__floats2half2_rn(v.x, v.y)),
                       h2_bits(__floats2half2_rn(v.z, v.w)));
    }
    __syncthreads();

    // ldmatrix smem addresses
    const uint32_t sA_base = (uint32_t)__cvta_generic_to_shared(&sA[0][0]);
    const uint32_t sB_base = (uint32_t)__cvta_generic_to_shared(&sB[0][0]);
    // A x4: rows (lane&15) of 16-row tile, col-halves by lane>>4
    const uint32_t aAddrBase =
        sA_base + (uint32_t)(((w * 16 + (lane & 15)) * APITCH + (lane >> 4) * 8) * 2);
    // B x2: rows (lane&7) of 8-row tile, col-halves by (lane>>3)&1
    const uint32_t bAddrBase =
        sB_base + (uint32_t)((((lane & 7)) * APITCH + ((lane >> 3) & 1) * 8) * 2);

    const int node0 = nodeBase + w * 16 + g;
    const int node1 = node0 + 8;
    const bool v0 = node0 < N_NODES, v1 = node1 < N_NODES;

    #pragma unroll
    for (int half = 0; half < 2; half++) {
        float d[8][4];
        #pragma unroll
        for (int nt = 0; nt < 8; nt++)
            d[nt][0] = d[nt][1] = d[nt][2] = d[nt][3] = 0.f;

        #pragma unroll
        for (int ks = 0; ks < 4; ks++) {
            uint32_t a0, a1, a2, a3;
            LDMATRIX_X4(a0, a1, a2, a3, aAddrBase + (uint32_t)(ks * 32));
            #pragma unroll
            for (int nt = 0; nt < 8; nt++) {
                uint32_t b0, b1;
                uint32_t baddr = bAddrBase +
                    (uint32_t)(((half * 64 + nt * 8) * APITCH + ks * 16) * 2);
                LDMATRIX_X2(b0, b1, baddr);
                asm volatile(
                    "mma.sync.aligned.m16n8k16.row.col.f32.f16.f16.f32 "
                    "{%0,%1,%2,%3}, {%4,%5,%6,%7}, {%8,%9}, {%0,%1,%2,%3};"
                    : "+f"(d[nt][0]), "+f"(d[nt][1]), "+f"(d[nt][2]), "+f"(d[nt][3])
                    : "r"(a0), "r"(a1), "r"(a2), "r"(a3), "r"(b0), "r"(b1));
            }
        }

        if (half == 0) {
            // self: cols 0-63, + bias -> out
            #pragma unroll
            for (int nt = 0; nt < 8; nt++) {
                int col = nt * 8 + tq * 2;
                float b0f = sBias[col], b1f = sBias[col + 1];
                if (v0)
                    *reinterpret_cast<float2*>(out + (size_t)node0 * D + col) =
                        make_float2(d[nt][0] + b0f, d[nt][1] + b1f);
                if (v1)
                    *reinterpret_cast<float2*>(out + (size_t)node1 * D + col) =
                        make_float2(d[nt][2] + b0f, d[nt][3] + b1f);
            }
        } else {
            // neigh: cols 64-127 -> fp16 g_gh
            #pragma unroll
            for (int nt = 0; nt < 8; nt++) {
                int ci = nt * 4 + tq;     // half2 index within row
                if (v0)
                    *reinterpret_cast<uint32_t*>(&g_gh[(size_t)node0 * 32 + ci]) =
                        h2_bits(__floats2half2_rn(d[nt][0], d[nt][1]));
                if (v1)
                    *reinterpret_cast<uint32_t*>(&g_gh[(size_t)node1 * 32 + ci]) =
                        h2_bits(__floats2half2_rn(d[nt][2], d[nt][3]));
            }
        }
    }
}

// ---------------------------------------------------------------------------
// K3: gather-aggregate (R12-proven). Warp/node, fp16 HFMA2, in-register sum.
//   lane = h*8 + c : h = edge slot (4 edges/step), c = dim group (8 dims).
//   RED-adds onto out (already holding self+bias from hmma_gemm).
// ---------------------------------------------------------------------------
__global__ __launch_bounds__(256) void aggregate_kernel(float* __restrict__ out) {
    int node = (blockIdx.x * blockDim.x + threadIdx.x) >> 5;
    if (node >= N_NODES) return;
    const int lane = threadIdx.x & 31;
    const int h = lane >> 3;       // edge slot 0..3
    const int c = lane & 7;        // dim group (8 dims)

    int cnt = g_cnt[node];
    if (cnt == 0) return;
    if (cnt > BUCKET) cnt = BUCKET;
    const float2* bucket = &g_csr[(size_t)node * BUCKET];

    uint32_t acc0 = 0, acc1 = 0, acc2 = 0, acc3 = 0;   // half2 accumulators
    float sum = 0.f;

    #pragma unroll 2
    for (int j = 0; j < cnt; j += 4) {
        int idx = j + h;
        float2 p = (idx < cnt) ? __ldg(&bucket[idx])
                               : make_float2(__int_as_float(0), 0.f);
        uint4 hv = __ldg(reinterpret_cast<const uint4*>(
            &g_gh[(size_t)__float_as_int(p.x) * 32 + c * 4]));
        uint32_t wh = h2_bits(__float2half2_rn(p.y));
        HFMA2(acc0, hv.x, wh);
        HFMA2(acc1, hv.y, wh);
        HFMA2(acc2, hv.z, wh);
        HFMA2(acc3, hv.w, wh);
        sum += p.y;
    }

    uint32_t o0, o1, o2, o3;
    o0 = __shfl_xor_sync(0xffffffffu, acc0, 8);  HADD2(acc0, acc0, o0);
    o1 = __shfl_xor_sync(0xffffffffu, acc1, 8);  HADD2(acc1, acc1, o1);
    o2 = __shfl_xor_sync(0xffffffffu, acc2, 8);  HADD2(acc2, acc2, o2);
    o3 = __shfl_xor_sync(0xffffffffu, acc3, 8);  HADD2(acc3, acc3, o3);
    o0 = __shfl_xor_sync(0xffffffffu, acc0, 16); HADD2(acc0, acc0, o0);
    o1 = __shfl_xor_sync(0xffffffffu, acc1, 16); HADD2(acc1, acc1, o1);
    o2 = __shfl_xor_sync(0xffffffffu, acc2, 16); HADD2(acc2, acc2, o2);
    o3 = __shfl_xor_sync(0xffffffffu, acc3, 16); HADD2(acc3, acc3, o3);
    sum += __shfl_xor_sync(0xffffffffu, sum, 8);
    sum += __shfl_xor_sync(0xffffffffu, sum, 16);

    if (h == 0) {
        const float inv = 1.0f / sum;
        float2 f0 = __half22float2(bits_h2(acc0));
        float2 f1 = __half22float2(bits_h2(acc1));
        float2 f2 = __half22float2(bits_h2(acc2));
        float2 f3 = __half22float2(bits_h2(acc3));
        float* p = out + (size_t)node * D + c * 8;
        asm volatile("red.global.add.v4.f32 [%0], {%1,%2,%3,%4};"
                     :: "l"(p), "f"(f0.x * inv), "f"(f0.y * inv),
                        "f"(f1.x * inv), "f"(f1.y * inv) : "memory");
        asm volatile("red.global.add.v4.f32 [%0], {%1,%2,%3,%4};"
                     :: "l"(p + 4), "f"(f2.x * inv), "f"(f2.y * inv),
                        "f"(f3.x * inv), "f"(f3.y * inv) : "memory");
    }
}

// ---------------------------------------------------------------------------
// Launch:  s2: hmma_gemm --evG-->           (writes out = self+bias, g_gh)
//          main: memset cnt; place; wait evG; aggregate (RED-adds onto out)
// ---------------------------------------------------------------------------
extern "C" void kernel_launch(void* const* d_in, const int* in_sizes, int n_in,
                              void* d_out, int out_size) {
    const float* feat = (const float*)d_in[0];
    const float* rel  = (const float*)d_in[1];
    const float* Ws   = (const float*)d_in[2];
    const float* bs   = (const float*)d_in[3];
    const float* Wn   = (const float*)d_in[4];
    const float* bn   = (const float*)d_in[5];
    const float* attn = (const float*)d_in[6];
    const int*   src  = (const int*)d_in[7];
    const int*   dst  = (const int*)d_in[8];
    float* out = (float*)d_out;

    static void*        cnt_addr = nullptr;
    static cudaStream_t s2;
    static cudaEvent_t  evFork, evG;
    if (!cnt_addr) {
        cudaGetSymbolAddress(&cnt_addr, g_cnt);
        cudaStreamCreateWithFlags(&s2, cudaStreamNonBlocking);
        cudaEventCreateWithFlags(&evFork, cudaEventDisableTiming);
        cudaEventCreateWithFlags(&evG,    cudaEventDisableTiming);
    }

    // Side stream: tensor-core fused GEMM (independent of edge path)
    cudaEventRecord(evFork, 0);
    cudaStreamWaitEvent(s2, evFork, 0);
    hmma_gemm_kernel<<<(N_NODES + 63) / 64, 128, 0, s2>>>(
        feat, Ws, bs, Wn, bn, out);
    cudaEventRecord(evG, s2);

    // Main: edge path
    cudaMemsetAsync(cnt_addr, 0, N_NODES * sizeof(int));
    place_kernel<<<(N_EDGES / 2 + 255) / 256, 256>>>(rel, attn, src, dst);

    // Aggregate needs hmma_gemm (out base + g_gh) and buckets
    cudaStreamWaitEvent(0, evG, 0);
    aggregate_kernel<<<(N_NODES * 32 + 255) / 256, 256>>>(out);
}